// round 2
// baseline (speedup 1.0000x reference)
#include <cuda_runtime.h>

// Problem constants
#define NB   32
#define NCH  3
#define HH   128
#define RR   127                 // output spatial size = H - K + 1
#define NPAIR 64                 // ceil(127/2) column pairs per row
#define NTHREADS_TOTAL (NB*RR*NPAIR)

// Circuit matrix U (16x16, row-major): state' = U * s
__device__ float g_U[256];

// ---------------------------------------------------------------------------
// f32x2 packed-math helpers (Blackwell sm_103a: 2 fp32 ops per instruction)
// ---------------------------------------------------------------------------
typedef unsigned long long f32x2_t;

__device__ __forceinline__ f32x2_t pk2(float lo, float hi) {
    f32x2_t r; asm("mov.b64 %0, {%1, %2};" : "=l"(r) : "f"(lo), "f"(hi)); return r;
}
__device__ __forceinline__ void upk2(f32x2_t v, float& lo, float& hi) {
    asm("mov.b64 {%0, %1}, %2;" : "=f"(lo), "=f"(hi) : "l"(v));
}
__device__ __forceinline__ f32x2_t mul2(f32x2_t a, f32x2_t b) {
    f32x2_t r; asm("mul.rn.f32x2 %0, %1, %2;" : "=l"(r) : "l"(a), "l"(b)); return r;
}
__device__ __forceinline__ f32x2_t add2(f32x2_t a, f32x2_t b) {
    f32x2_t r; asm("add.rn.f32x2 %0, %1, %2;" : "=l"(r) : "l"(a), "l"(b)); return r;
}
__device__ __forceinline__ f32x2_t sub2(f32x2_t a, f32x2_t b) {
    f32x2_t r; asm("sub.rn.f32x2 %0, %1, %2;" : "=l"(r) : "l"(a), "l"(b)); return r;
}
__device__ __forceinline__ f32x2_t fma2(f32x2_t a, f32x2_t b, f32x2_t c) {
    f32x2_t r; asm("fma.rn.f32x2 %0, %1, %2, %3;" : "=l"(r) : "l"(a), "l"(b), "l"(c)); return r;
}

// ---------------------------------------------------------------------------
// Prep: build U by evolving the 16 basis columns through the circuit.
// Thread j owns column j. State index = (a<<3)|(b<<2)|(c<<1)|d.
// ---------------------------------------------------------------------------
__global__ void prep_kernel(const float* __restrict__ w) {
    int j = threadIdx.x;
    if (j >= 16) return;
    float m[16];
#pragma unroll
    for (int i = 0; i < 16; i++) m[i] = (i == j) ? 1.0f : 0.0f;

    for (int layer = 0; layer < 4; layer++) {
#pragma unroll
        for (int q = 0; q < 4; q++) {
            float t = 0.5f * w[layer * 4 + q];
            float c = cosf(t), s = sinf(t);
            int mask = 8 >> q;
#pragma unroll
            for (int i0 = 0; i0 < 16; i0++) {
                if (i0 & mask) continue;
                int i1 = i0 | mask;
                float a0 = m[i0], a1 = m[i1];
                m[i0] = c * a0 - s * a1;
                m[i1] = s * a0 + c * a1;
            }
        }
        // CNOT(0,1): ctrl bit 8, tgt bit 4
#pragma unroll
        for (int i = 0; i < 16; i++)
            if ((i & 8) && !(i & 4)) { float tt = m[i]; m[i] = m[i | 4]; m[i | 4] = tt; }
        // CNOT(2,3): ctrl bit 2, tgt bit 1
#pragma unroll
        for (int i = 0; i < 16; i++)
            if ((i & 2) && !(i & 1)) { float tt = m[i]; m[i] = m[i | 1]; m[i | 1] = tt; }
        // CNOT(1,2): ctrl bit 4, tgt bit 2
#pragma unroll
        for (int i = 0; i < 16; i++)
            if ((i & 4) && !(i & 2)) { float tt = m[i]; m[i] = m[i | 2]; m[i | 2] = tt; }
    }
#pragma unroll
    for (int i = 0; i < 16; i++) g_U[i * 16 + j] = m[i];
}

// ---------------------------------------------------------------------------
// Main: one thread per PAIR of horizontally adjacent outputs (b, i, 2j / 2j+1).
// All state-prep / matvec / square / reduction math in packed f32x2
// (lane lo = left output, lane hi = right output).
// U held in shared memory pre-duplicated as {u,u} so LDS.128 yields two
// ready packed operands.
// ---------------------------------------------------------------------------
__global__ void __launch_bounds__(256) rqcnn_main(const float* __restrict__ x,
                                                  float* __restrict__ out) {
    __shared__ __align__(16) f32x2_t sU2[256];
    {
        float u = g_U[threadIdx.x];
        sU2[threadIdx.x] = pk2(u, u);
    }
    __syncthreads();

    int gid = blockIdx.x * 256 + threadIdx.x;
    if (gid >= NTHREADS_TOTAL) return;

    int pj = gid & (NPAIR - 1);
    int t  = gid >> 6;            // NPAIR == 64
    int i  = t % RR;
    int b  = t / RR;
    int c0 = pj * 2;
    // third column: c0+2, clamped in-bounds for the edge pair (value unused there)
    int off2 = (c0 + 2 > HH - 1) ? 1 : 2;

    const float HPI = 1.57079632679489662f;  // pi/2

    f32x2_t P[16];
#pragma unroll
    for (int r = 0; r < 16; r++) P[r] = 0ULL;

    for (int c = 0; c < NCH; c++) {
        const float* px = x + (((b * NCH + c) * HH) + i) * HH + c0;
        float2 r0 = *reinterpret_cast<const float2*>(px);         // (i, c0), (i, c0+1)
        float  p02 = px[off2];                                    // (i, c0+2)
        float2 r1 = *reinterpret_cast<const float2*>(px + HH);    // (i+1, c0), (i+1, c0+1)
        float  p12 = px[HH + off2];                               // (i+1, c0+2)

        float c00, s00, c01, s01, c02, s02, c10, s10, c11, s11, c12, s12;
        __sincosf(r0.x * HPI, &s00, &c00);
        __sincosf(r0.y * HPI, &s01, &c01);
        __sincosf(p02  * HPI, &s02, &c02);
        __sincosf(r1.x * HPI, &s10, &c10);
        __sincosf(r1.y * HPI, &s11, &c11);
        __sincosf(p12  * HPI, &s12, &c12);

        // qubit amplitudes, packed over (left out, right out)
        f32x2_t ca = pk2(c00, c01), sa = pk2(s00, s01);   // qubit a: (i,  j)
        f32x2_t cb = pk2(c01, c02), sb = pk2(s01, s02);   // qubit b: (i,  j+1)
        f32x2_t cc = pk2(c10, c11), sc = pk2(s10, s11);   // qubit c: (i+1,j)
        f32x2_t cd = pk2(c11, c12), sd = pk2(s11, s12);   // qubit d: (i+1,j+1)

        f32x2_t ab00 = mul2(ca, cb), ab01 = mul2(ca, sb);
        f32x2_t ab10 = mul2(sa, cb), ab11 = mul2(sa, sb);
        f32x2_t cd00 = mul2(cc, cd), cd01 = mul2(cc, sd);
        f32x2_t cd10 = mul2(sc, cd), cd11 = mul2(sc, sd);

        f32x2_t s[16];
        s[0]  = mul2(ab00, cd00); s[1]  = mul2(ab00, cd01); s[2]  = mul2(ab00, cd10); s[3]  = mul2(ab00, cd11);
        s[4]  = mul2(ab01, cd00); s[5]  = mul2(ab01, cd01); s[6]  = mul2(ab01, cd10); s[7]  = mul2(ab01, cd11);
        s[8]  = mul2(ab10, cd00); s[9]  = mul2(ab10, cd01); s[10] = mul2(ab10, cd10); s[11] = mul2(ab10, cd11);
        s[12] = mul2(ab11, cd00); s[13] = mul2(ab11, cd01); s[14] = mul2(ab11, cd10); s[15] = mul2(ab11, cd11);

#pragma unroll
        for (int r = 0; r < 16; r++) {
            const ulonglong2* row = reinterpret_cast<const ulonglong2*>(sU2 + r * 16);
            ulonglong2 q0 = row[0], q1 = row[1], q2 = row[2], q3 = row[3];
            ulonglong2 q4 = row[4], q5 = row[5], q6 = row[6], q7 = row[7];
            f32x2_t y;
            y = mul2(q0.x, s[0]);
            y = fma2(q0.y, s[1],  y);
            y = fma2(q1.x, s[2],  y);
            y = fma2(q1.y, s[3],  y);
            y = fma2(q2.x, s[4],  y);
            y = fma2(q2.y, s[5],  y);
            y = fma2(q3.x, s[6],  y);
            y = fma2(q3.y, s[7],  y);
            y = fma2(q4.x, s[8],  y);
            y = fma2(q4.y, s[9],  y);
            y = fma2(q5.x, s[10], y);
            y = fma2(q5.y, s[11], y);
            y = fma2(q6.x, s[12], y);
            y = fma2(q6.y, s[13], y);
            y = fma2(q7.x, s[14], y);
            y = fma2(q7.y, s[15], y);
            P[r] = fma2(y, y, P[r]);
        }
    }

    // Signed butterfly reductions over P (packed): z_q = sum_i sgn(bit_{3-q}(i)) P_i
    f32x2_t z3 = add2(add2(add2(sub2(P[0],  P[1]),  sub2(P[2],  P[3])),
                           add2(sub2(P[4],  P[5]),  sub2(P[6],  P[7]))),
                      add2(add2(sub2(P[8],  P[9]),  sub2(P[10], P[11])),
                           add2(sub2(P[12], P[13]), sub2(P[14], P[15]))));
    f32x2_t e0 = add2(P[0],  P[1]),  e1 = add2(P[2],  P[3]);
    f32x2_t e2 = add2(P[4],  P[5]),  e3 = add2(P[6],  P[7]);
    f32x2_t e4 = add2(P[8],  P[9]),  e5 = add2(P[10], P[11]);
    f32x2_t e6 = add2(P[12], P[13]), e7 = add2(P[14], P[15]);
    f32x2_t z2 = add2(add2(sub2(e0, e1), sub2(e2, e3)),
                      add2(sub2(e4, e5), sub2(e6, e7)));
    f32x2_t f0 = add2(e0, e1), f1 = add2(e2, e3), f2 = add2(e4, e5), f3 = add2(e6, e7);
    f32x2_t z1 = add2(sub2(f0, f1), sub2(f2, f3));
    f32x2_t z0 = sub2(add2(f0, f1), add2(f2, f3));

    float z0l, z0h, z1l, z1h, z2l, z2h, z3l, z3h;
    upk2(z0, z0l, z0h);
    upk2(z1, z1l, z1h);
    upk2(z2, z2l, z2h);
    upk2(z3, z3l, z3h);

    // Output: q_out[B,R,R,DEPTH] contiguous (reinterpret of [B,DEPTH,R,R])
    int loc0 = (b * RR + i) * RR + c0;
    reinterpret_cast<float4*>(out)[loc0] = make_float4(z0l, z1l, z2l, z3l);
    if (c0 + 1 < RR)
        reinterpret_cast<float4*>(out)[loc0 + 1] = make_float4(z0h, z1h, z2h, z3h);
}

extern "C" void kernel_launch(void* const* d_in, const int* in_sizes, int n_in,
                              void* d_out, int out_size) {
    const float* x = (const float*)d_in[0];   // [32,3,128,128] float32
    const float* w = (const float*)d_in[1];   // [4,4] float32
    float* out = (float*)d_out;               // [32,4,127,127] float32

    prep_kernel<<<1, 16>>>(w);
    int blocks = (NTHREADS_TOTAL + 255) / 256;
    rqcnn_main<<<blocks, 256>>>(x, out);
}

// round 3
// speedup vs baseline: 1.6761x; 1.6761x over previous
#include <cuda_runtime.h>

// Problem constants
#define NB   32
#define NCH  3
#define HH   128
#define RR   127                 // output spatial size = H - K + 1
#define NPAIR 64                 // ceil(127/2) column pairs per row
#define NTHREADS_TOTAL (NB*RR*NPAIR)

// ---------------------------------------------------------------------------
// f32x2 packed-math helpers (Blackwell sm_103a: 2 fp32 ops per instruction)
// ---------------------------------------------------------------------------
typedef unsigned long long f32x2_t;

__device__ __forceinline__ f32x2_t pk2(float lo, float hi) {
    f32x2_t r; asm("mov.b64 %0, {%1, %2};" : "=l"(r) : "f"(lo), "f"(hi)); return r;
}
__device__ __forceinline__ void upk2(f32x2_t v, float& lo, float& hi) {
    asm("mov.b64 {%0, %1}, %2;" : "=f"(lo), "=f"(hi) : "l"(v));
}
__device__ __forceinline__ f32x2_t mul2(f32x2_t a, f32x2_t b) {
    f32x2_t r; asm("mul.rn.f32x2 %0, %1, %2;" : "=l"(r) : "l"(a), "l"(b)); return r;
}
__device__ __forceinline__ f32x2_t add2(f32x2_t a, f32x2_t b) {
    f32x2_t r; asm("add.rn.f32x2 %0, %1, %2;" : "=l"(r) : "l"(a), "l"(b)); return r;
}
__device__ __forceinline__ f32x2_t sub2(f32x2_t a, f32x2_t b) {
    f32x2_t r; asm("sub.rn.f32x2 %0, %1, %2;" : "=l"(r) : "l"(a), "l"(b)); return r;
}
__device__ __forceinline__ f32x2_t fma2(f32x2_t a, f32x2_t b, f32x2_t c) {
    f32x2_t r; asm("fma.rn.f32x2 %0, %1, %2, %3;" : "=l"(r) : "l"(a), "l"(b), "l"(c)); return r;
}

// ---------------------------------------------------------------------------
// Main kernel. One thread per PAIR of horizontally adjacent outputs.
// Threads 0-15 of each block first build the 16x16 circuit matrix U in shared
// (duplicated as {u,u} for packed LDS.128 operands), then all threads do
// packed state-prep -> matvec -> square -> signed z-accumulation.
// Live set kept small: s[16] packed + z[4] packed, no persistent P[16].
// ---------------------------------------------------------------------------
__global__ void __launch_bounds__(256) rqcnn_main(const float* __restrict__ x,
                                                  const float* __restrict__ w,
                                                  float* __restrict__ out) {
    __shared__ __align__(16) f32x2_t sU2[256];

    // --- build U in shared: thread j owns column j ---
    if (threadIdx.x < 16) {
        int j = threadIdx.x;
        float m[16];
#pragma unroll
        for (int i = 0; i < 16; i++) m[i] = (i == j) ? 1.0f : 0.0f;
        for (int layer = 0; layer < 4; layer++) {
#pragma unroll
            for (int q = 0; q < 4; q++) {
                float t = 0.5f * w[layer * 4 + q];
                float c = cosf(t), s = sinf(t);
                int mask = 8 >> q;
#pragma unroll
                for (int i0 = 0; i0 < 16; i0++) {
                    if (i0 & mask) continue;
                    int i1 = i0 | mask;
                    float a0 = m[i0], a1 = m[i1];
                    m[i0] = c * a0 - s * a1;
                    m[i1] = s * a0 + c * a1;
                }
            }
            // CNOT(0,1): ctrl bit 8, tgt bit 4
#pragma unroll
            for (int i = 0; i < 16; i++)
                if ((i & 8) && !(i & 4)) { float tt = m[i]; m[i] = m[i | 4]; m[i | 4] = tt; }
            // CNOT(2,3): ctrl bit 2, tgt bit 1
#pragma unroll
            for (int i = 0; i < 16; i++)
                if ((i & 2) && !(i & 1)) { float tt = m[i]; m[i] = m[i | 1]; m[i | 1] = tt; }
            // CNOT(1,2): ctrl bit 4, tgt bit 2
#pragma unroll
            for (int i = 0; i < 16; i++)
                if ((i & 4) && !(i & 2)) { float tt = m[i]; m[i] = m[i | 2]; m[i | 2] = tt; }
        }
#pragma unroll
        for (int i = 0; i < 16; i++) sU2[i * 16 + j] = pk2(m[i], m[i]);
    }
    __syncthreads();

    int gid = blockIdx.x * 256 + threadIdx.x;
    if (gid >= NTHREADS_TOTAL) return;

    int pj = gid & (NPAIR - 1);
    int t  = gid >> 6;            // NPAIR == 64
    int i  = t % RR;
    int b  = t / RR;
    int c0 = pj * 2;
    // third column c0+2, clamped for the last (half) pair; value unused there
    int off2 = (c0 + 2 > HH - 1) ? 1 : 2;

    const float HPI = 1.57079632679489662f;  // pi/2

    f32x2_t z0 = 0ULL, z1 = 0ULL, z2 = 0ULL, z3 = 0ULL;

#pragma unroll
    for (int c = 0; c < NCH; c++) {
        const float* px = x + (((b * NCH + c) * HH) + i) * HH + c0;
        float2 r0 = *reinterpret_cast<const float2*>(px);         // (i,   c0..c0+1)
        float  p02 = px[off2];                                    // (i,   c0+2)
        float2 r1 = *reinterpret_cast<const float2*>(px + HH);    // (i+1, c0..c0+1)
        float  p12 = px[HH + off2];                               // (i+1, c0+2)

        float c00, s00, c01, s01, c02, s02, c10, s10, c11, s11, c12, s12;
        __sincosf(r0.x * HPI, &s00, &c00);
        __sincosf(r0.y * HPI, &s01, &c01);
        __sincosf(p02  * HPI, &s02, &c02);
        __sincosf(r1.x * HPI, &s10, &c10);
        __sincosf(r1.y * HPI, &s11, &c11);
        __sincosf(p12  * HPI, &s12, &c12);

        // packed qubit amplitudes over (left out, right out)
        f32x2_t ca = pk2(c00, c01), sa = pk2(s00, s01);   // qubit a: (i,  j)
        f32x2_t cb = pk2(c01, c02), sb = pk2(s01, s02);   // qubit b: (i,  j+1)
        f32x2_t cc = pk2(c10, c11), sc = pk2(s10, s11);   // qubit c: (i+1,j)
        f32x2_t cd = pk2(c11, c12), sd = pk2(s11, s12);   // qubit d: (i+1,j+1)

        f32x2_t ab00 = mul2(ca, cb), ab01 = mul2(ca, sb);
        f32x2_t ab10 = mul2(sa, cb), ab11 = mul2(sa, sb);
        f32x2_t cd00 = mul2(cc, cd), cd01 = mul2(cc, sd);
        f32x2_t cd10 = mul2(sc, cd), cd11 = mul2(sc, sd);

        f32x2_t s[16];
        s[0]  = mul2(ab00, cd00); s[1]  = mul2(ab00, cd01); s[2]  = mul2(ab00, cd10); s[3]  = mul2(ab00, cd11);
        s[4]  = mul2(ab01, cd00); s[5]  = mul2(ab01, cd01); s[6]  = mul2(ab01, cd10); s[7]  = mul2(ab01, cd11);
        s[8]  = mul2(ab10, cd00); s[9]  = mul2(ab10, cd01); s[10] = mul2(ab10, cd10); s[11] = mul2(ab10, cd11);
        s[12] = mul2(ab11, cd00); s[13] = mul2(ab11, cd01); s[14] = mul2(ab11, cd10); s[15] = mul2(ab11, cd11);

#pragma unroll
        for (int r = 0; r < 16; r++) {
            const ulonglong2* row = reinterpret_cast<const ulonglong2*>(sU2 + r * 16);
            ulonglong2 q0 = row[0], q1 = row[1], q2 = row[2], q3 = row[3];
            f32x2_t y;
            y = mul2(q0.x, s[0]);
            y = fma2(q0.y, s[1],  y);
            y = fma2(q1.x, s[2],  y);
            y = fma2(q1.y, s[3],  y);
            y = fma2(q2.x, s[4],  y);
            y = fma2(q2.y, s[5],  y);
            y = fma2(q3.x, s[6],  y);
            y = fma2(q3.y, s[7],  y);
            ulonglong2 q4 = row[4], q5 = row[5], q6 = row[6], q7 = row[7];
            y = fma2(q4.x, s[8],  y);
            y = fma2(q4.y, s[9],  y);
            y = fma2(q5.x, s[10], y);
            y = fma2(q5.y, s[11], y);
            y = fma2(q6.x, s[12], y);
            y = fma2(q6.y, s[13], y);
            y = fma2(q7.x, s[14], y);
            y = fma2(q7.y, s[15], y);
            f32x2_t p = mul2(y, y);
            // signed accumulation: z_q sign = -1 iff bit (3-q) of r is set
            z0 = (r & 8) ? sub2(z0, p) : add2(z0, p);
            z1 = (r & 4) ? sub2(z1, p) : add2(z1, p);
            z2 = (r & 2) ? sub2(z2, p) : add2(z2, p);
            z3 = (r & 1) ? sub2(z3, p) : add2(z3, p);
        }
    }

    float z0l, z0h, z1l, z1h, z2l, z2h, z3l, z3h;
    upk2(z0, z0l, z0h);
    upk2(z1, z1l, z1h);
    upk2(z2, z2l, z2h);
    upk2(z3, z3l, z3h);

    // Output: q_out[B,R,R,DEPTH] contiguous (memory reinterpret of [B,DEPTH,R,R])
    int loc0 = (b * RR + i) * RR + c0;
    reinterpret_cast<float4*>(out)[loc0] = make_float4(z0l, z1l, z2l, z3l);
    if (c0 + 1 < RR)
        reinterpret_cast<float4*>(out)[loc0 + 1] = make_float4(z0h, z1h, z2h, z3h);
}

extern "C" void kernel_launch(void* const* d_in, const int* in_sizes, int n_in,
                              void* d_out, int out_size) {
    const float* x = (const float*)d_in[0];   // [32,3,128,128] float32
    const float* w = (const float*)d_in[1];   // [4,4] float32
    float* out = (float*)d_out;               // [32,4,127,127] float32

    int blocks = (NTHREADS_TOTAL + 255) / 256;
    rqcnn_main<<<blocks, 256>>>(x, w, out);
}

// round 5
// speedup vs baseline: 6.1250x; 3.6542x over previous
#include <cuda_runtime.h>

// Problem constants
#define NB   32
#define NCH  3
#define HH   128
#define RR   127                 // output spatial size = H - K + 1
#define NLOC (NB*RR*RR)

// ---------------------------------------------------------------------------
// f32x2 packed-math helpers (sm_103a: 2 fp32 ops per instruction)
// ---------------------------------------------------------------------------
typedef unsigned long long f32x2_t;

__device__ __forceinline__ f32x2_t pk2(float lo, float hi) {
    f32x2_t r; asm("mov.b64 %0, {%1, %2};" : "=l"(r) : "f"(lo), "f"(hi)); return r;
}
__device__ __forceinline__ void upk2(f32x2_t v, float& lo, float& hi) {
    asm("mov.b64 {%0, %1}, %2;" : "=f"(lo), "=f"(hi) : "l"(v));
}
__device__ __forceinline__ f32x2_t mul2(f32x2_t a, f32x2_t b) {
    f32x2_t r; asm("mul.rn.f32x2 %0, %1, %2;" : "=l"(r) : "l"(a), "l"(b)); return r;
}
__device__ __forceinline__ f32x2_t fma2(f32x2_t a, f32x2_t b, f32x2_t c) {
    f32x2_t r; asm("fma.rn.f32x2 %0, %1, %2, %3;" : "=l"(r) : "l"(a), "l"(b), "l"(c)); return r;
}

// ---------------------------------------------------------------------------
// One kernel. Threads 0-15 of each block build the 16x16 circuit matrix U in
// shared memory (plain floats, row-major), then every thread computes ONE
// output location:
//   s (16 components, stored as 8 natural f32x2 pairs over the qubit-d bit)
//   y_r = U_r . s  via 8 fma2 + horizontal add;  P_r += y_r^2 over channels
//   z = signed butterfly over P
// Global pixel loads are SCALAR (4B) — patch base x+...+j has only 4-byte
// alignment for odd j, so float2 loads fault.
// ---------------------------------------------------------------------------
__global__ void __launch_bounds__(256) rqcnn_main(const float* __restrict__ x,
                                                  const float* __restrict__ w,
                                                  float* __restrict__ out) {
    __shared__ __align__(16) float sU[256];

    // --- build U: thread j owns column j ---
    if (threadIdx.x < 16) {
        int j = threadIdx.x;
        float m[16];
#pragma unroll
        for (int i = 0; i < 16; i++) m[i] = (i == j) ? 1.0f : 0.0f;
        for (int layer = 0; layer < 4; layer++) {
#pragma unroll
            for (int q = 0; q < 4; q++) {
                float t = 0.5f * w[layer * 4 + q];
                float c = cosf(t), s = sinf(t);
                int mask = 8 >> q;
#pragma unroll
                for (int i0 = 0; i0 < 16; i0++) {
                    if (i0 & mask) continue;
                    int i1 = i0 | mask;
                    float a0 = m[i0], a1 = m[i1];
                    m[i0] = c * a0 - s * a1;
                    m[i1] = s * a0 + c * a1;
                }
            }
            // CNOT(0,1): ctrl bit 8, tgt bit 4
#pragma unroll
            for (int i = 0; i < 16; i++)
                if ((i & 8) && !(i & 4)) { float tt = m[i]; m[i] = m[i | 4]; m[i | 4] = tt; }
            // CNOT(2,3): ctrl bit 2, tgt bit 1
#pragma unroll
            for (int i = 0; i < 16; i++)
                if ((i & 2) && !(i & 1)) { float tt = m[i]; m[i] = m[i | 1]; m[i | 1] = tt; }
            // CNOT(1,2): ctrl bit 4, tgt bit 2
#pragma unroll
            for (int i = 0; i < 16; i++)
                if ((i & 4) && !(i & 2)) { float tt = m[i]; m[i] = m[i | 2]; m[i | 2] = tt; }
        }
#pragma unroll
        for (int i = 0; i < 16; i++) sU[i * 16 + j] = m[i];
    }
    __syncthreads();

    int gid = blockIdx.x * 256 + threadIdx.x;
    if (gid >= NLOC) return;

    int j  = gid % RR;
    int t2 = gid / RR;
    int i  = t2 % RR;
    int b  = t2 / RR;

    const float HPI = 1.57079632679489662f;  // pi/2

    float P[16];
#pragma unroll
    for (int r = 0; r < 16; r++) P[r] = 0.0f;

#pragma unroll
    for (int c = 0; c < NCH; c++) {
        const float* px = x + (((b * NCH + c) * HH) + i) * HH + j;
        float p00 = px[0];
        float p01 = px[1];
        float p10 = px[HH];
        float p11 = px[HH + 1];

        float ca, sa, cb, sb, cc, sc, cd, sd;
        __sincosf(p00 * HPI, &sa, &ca);   // qubit a: (i,   j)
        __sincosf(p01 * HPI, &sb, &cb);   // qubit b: (i,   j+1)
        __sincosf(p10 * HPI, &sc, &cc);   // qubit c: (i+1, j)
        __sincosf(p11 * HPI, &sd, &cd);   // qubit d: (i+1, j+1)

        // ab[ia*2+ib], cd pairs over qubit-d bit
        float ab0 = ca * cb, ab1 = ca * sb, ab2 = sa * cb, ab3 = sa * sb;
        f32x2_t cdp0 = pk2(cc * cd, cc * sd);   // (cd[0], cd[1])  ic=0
        f32x2_t cdp1 = pk2(sc * cd, sc * sd);   // (cd[2], cd[3])  ic=1

        // sp[p] = (s[2p], s[2p+1]), p = ia*4 + ib*2 + ic
        f32x2_t d0 = pk2(ab0, ab0), d1 = pk2(ab1, ab1);
        f32x2_t d2 = pk2(ab2, ab2), d3 = pk2(ab3, ab3);
        f32x2_t sp[8];
        sp[0] = mul2(d0, cdp0); sp[1] = mul2(d0, cdp1);
        sp[2] = mul2(d1, cdp0); sp[3] = mul2(d1, cdp1);
        sp[4] = mul2(d2, cdp0); sp[5] = mul2(d2, cdp1);
        sp[6] = mul2(d3, cdp0); sp[7] = mul2(d3, cdp1);

#pragma unroll
        for (int r = 0; r < 16; r++) {
            const ulonglong2* row = reinterpret_cast<const ulonglong2*>(sU + r * 16);
            ulonglong2 u0 = row[0];     // pairs (0,1),(2,3)
            ulonglong2 u1 = row[1];     // pairs (4,5),(6,7)
            f32x2_t y2;
            y2 = mul2(u0.x, sp[0]);
            y2 = fma2(u0.y, sp[1], y2);
            y2 = fma2(u1.x, sp[2], y2);
            y2 = fma2(u1.y, sp[3], y2);
            ulonglong2 u2 = row[2];     // pairs (8,9),(10,11)
            ulonglong2 u3 = row[3];     // pairs (12,13),(14,15)
            y2 = fma2(u2.x, sp[4], y2);
            y2 = fma2(u2.y, sp[5], y2);
            y2 = fma2(u3.x, sp[6], y2);
            y2 = fma2(u3.y, sp[7], y2);
            float ylo, yhi;
            upk2(y2, ylo, yhi);
            float y = ylo + yhi;
            P[r] = fmaf(y, y, P[r]);
        }
    }

    // Signed butterfly: z_q = sum_r sgn(bit_{3-q}(r)) * P_r
    float z3 = (P[0] - P[1]) + (P[2] - P[3]) + (P[4] - P[5]) + (P[6] - P[7])
             + (P[8] - P[9]) + (P[10] - P[11]) + (P[12] - P[13]) + (P[14] - P[15]);
    float e0 = P[0]  + P[1],  e1 = P[2]  + P[3],  e2 = P[4]  + P[5],  e3 = P[6]  + P[7];
    float e4 = P[8]  + P[9],  e5 = P[10] + P[11], e6 = P[12] + P[13], e7 = P[14] + P[15];
    float z2 = (e0 - e1) + (e2 - e3) + (e4 - e5) + (e6 - e7);
    float f0 = e0 + e1, f1 = e2 + e3, f2 = e4 + e5, f3 = e6 + e7;
    float z1 = (f0 - f1) + (f2 - f3);
    float z0 = (f0 + f1) - (f2 + f3);

    // Output: q_out[B,R,R,DEPTH] contiguous (memory reinterpret of [B,DEPTH,R,R])
    reinterpret_cast<float4*>(out)[gid] = make_float4(z0, z1, z2, z3);
}

extern "C" void kernel_launch(void* const* d_in, const int* in_sizes, int n_in,
                              void* d_out, int out_size) {
    const float* x = (const float*)d_in[0];   // [32,3,128,128] float32
    const float* w = (const float*)d_in[1];   // [4,4] float32
    float* out = (float*)d_out;               // [32,4,127,127] float32

    int blocks = (NLOC + 255) / 256;
    rqcnn_main<<<blocks, 256>>>(x, w, out);
}